// round 1
// baseline (speedup 1.0000x reference)
#include <cuda_runtime.h>

// Problem constants (fixed shapes from reference)
#define B_    2
#define S_    512
#define D_    512
#define MTOK  (B_ * S_)     // 1024 tokens
#define NTOT  (3 * D_)      // 1536 (w1 | w2 | w3 concatenated)
#define EPS_  1e-5f

// Scratch for the three projections: P[m][0:512)=w1, [512:1024)=w2, [1024:1536)=w3
__device__ float g_P[MTOK * NTOT];   // 6 MB static device scratch (allowed)

// ---------------------------------------------------------------------------
// Kernel 1: P[m,n] = sum_k X[m,k] * W[n,k]   (NT GEMM, K contiguous for both)
// BM=BN=64, BK=32, 256 threads (16x16), 4x4 microtile per thread.
// ---------------------------------------------------------------------------
#define BM 64
#define BN 64
#define BK 32
#define TM 4
#define TN 4

__global__ __launch_bounds__(256) void gemm3_kernel(
    const float* __restrict__ X,
    const float* __restrict__ Win,
    const float* __restrict__ Wout,
    const float* __restrict__ Wb)
{
    __shared__ float As[BK][BM + 1];   // +1 pad: conflict-free transposed stores
    __shared__ float Bs[BK][BN + 1];

    const int tid = threadIdx.x;
    const int tx  = tid & 15;          // 0..15  -> N direction
    const int ty  = tid >> 4;          // 0..15  -> M direction
    const int m0  = blockIdx.x * BM;
    const int n0  = blockIdx.y * BN;

    // Each 64-wide N tile lies entirely within one weight matrix (512 % 64 == 0)
    const float* Wsel = (n0 < D_) ? Win : (n0 < 2 * D_ ? Wout : Wb);
    const int nb = n0 & (D_ - 1);

    float acc[TM][TN];
    #pragma unroll
    for (int i = 0; i < TM; i++)
        #pragma unroll
        for (int j = 0; j < TN; j++) acc[i][j] = 0.f;

    for (int k0 = 0; k0 < D_; k0 += BK) {
        // Load A tile: 64x32 floats = 512 float4, 2 per thread
        #pragma unroll
        for (int it = 0; it < 2; ++it) {
            int idx = tid + it * 256;           // 0..511
            int row = idx >> 3;                 // 0..63
            int kq  = idx & 7;                  // 0..7 (float4 group within BK)
            float4 v = *reinterpret_cast<const float4*>(
                &X[(m0 + row) * D_ + k0 + kq * 4]);
            As[kq * 4 + 0][row] = v.x;
            As[kq * 4 + 1][row] = v.y;
            As[kq * 4 + 2][row] = v.z;
            As[kq * 4 + 3][row] = v.w;
        }
        // Load B tile: 64x32 floats
        #pragma unroll
        for (int it = 0; it < 2; ++it) {
            int idx = tid + it * 256;
            int row = idx >> 3;
            int kq  = idx & 7;
            float4 v = *reinterpret_cast<const float4*>(
                &Wsel[(nb + row) * D_ + k0 + kq * 4]);
            Bs[kq * 4 + 0][row] = v.x;
            Bs[kq * 4 + 1][row] = v.y;
            Bs[kq * 4 + 2][row] = v.z;
            Bs[kq * 4 + 3][row] = v.w;
        }
        __syncthreads();

        #pragma unroll
        for (int k = 0; k < BK; ++k) {
            float a[TM], b[TN];
            #pragma unroll
            for (int i = 0; i < TM; i++) a[i] = As[k][ty * TM + i];
            #pragma unroll
            for (int j = 0; j < TN; j++) b[j] = Bs[k][tx * TN + j];
            #pragma unroll
            for (int i = 0; i < TM; i++)
                #pragma unroll
                for (int j = 0; j < TN; j++)
                    acc[i][j] = fmaf(a[i], b[j], acc[i][j]);
        }
        __syncthreads();
    }

    #pragma unroll
    for (int i = 0; i < TM; i++) {
        int m = m0 + ty * TM + i;
        #pragma unroll
        for (int j = 0; j < TN; j++)
            g_P[m * NTOT + n0 + tx * TN + j] = acc[i][j];
    }
}

// ---------------------------------------------------------------------------
// Kernel 2: per-token closed-form epilogue.
//   mu1 = mean(w1); var1 = mean(w1^2) - mu1^2  (biased)
//   s   = dot(w1, x) - mu1 * sum(x)
//   b   = (w3 - mean(w3)) * rsqrt(var(w3) + eps)
//   y_i = w2_i * s * rsqrt(w2_i^2 * var1 + eps) + b_i
// ---------------------------------------------------------------------------
__global__ __launch_bounds__(256) void finalize_kernel(
    const float* __restrict__ X, float* __restrict__ Y)
{
    __shared__ float red[6][8];
    const int m   = blockIdx.x;
    const int tid = threadIdx.x;
    const float* x = X + m * D_;
    const float* p = g_P + m * NTOT;   // w1 | w2 | w3

    float sw1 = 0.f, sw1q = 0.f, sx = 0.f, sw1x = 0.f, sw3 = 0.f, sw3q = 0.f;
    #pragma unroll
    for (int it = 0; it < 2; ++it) {
        int i = tid + it * 256;
        float a  = p[i];            // w1[i]
        float xx = x[i];
        float c  = p[2 * D_ + i];   // w3[i]
        sw1  += a;
        sw1q += a * a;
        sx   += xx;
        sw1x += a * xx;
        sw3  += c;
        sw3q += c * c;
    }
    #pragma unroll
    for (int o = 16; o; o >>= 1) {
        sw1  += __shfl_xor_sync(0xffffffffu, sw1,  o);
        sw1q += __shfl_xor_sync(0xffffffffu, sw1q, o);
        sx   += __shfl_xor_sync(0xffffffffu, sx,   o);
        sw1x += __shfl_xor_sync(0xffffffffu, sw1x, o);
        sw3  += __shfl_xor_sync(0xffffffffu, sw3,  o);
        sw3q += __shfl_xor_sync(0xffffffffu, sw3q, o);
    }
    const int warp = tid >> 5, lane = tid & 31;
    if (lane == 0) {
        red[0][warp] = sw1;  red[1][warp] = sw1q; red[2][warp] = sx;
        red[3][warp] = sw1x; red[4][warp] = sw3;  red[5][warp] = sw3q;
    }
    __syncthreads();

    float r[6];
    #pragma unroll
    for (int j = 0; j < 6; j++) {
        float t = 0.f;
        #pragma unroll
        for (int w = 0; w < 8; w++) t += red[j][w];
        r[j] = t;
    }

    const float invD = 1.0f / (float)D_;
    float mu1  = r[0] * invD;
    float var1 = fmaxf(r[1] * invD - mu1 * mu1, 0.f);
    float s    = r[3] - mu1 * r[2];
    float mu3  = r[4] * invD;
    float var3 = fmaxf(r[5] * invD - mu3 * mu3, 0.f);
    float inv3 = rsqrtf(var3 + EPS_);

    #pragma unroll
    for (int it = 0; it < 2; ++it) {
        int i = tid + it * 256;
        float v2 = p[D_ + i];        // w2[i]
        float c  = p[2 * D_ + i];    // w3[i]
        Y[m * D_ + i] = v2 * s * rsqrtf(v2 * v2 * var1 + EPS_)
                      + (c - mu3) * inv3;
    }
}

// ---------------------------------------------------------------------------
extern "C" void kernel_launch(void* const* d_in, const int* in_sizes, int n_in,
                              void* d_out, int out_size)
{
    const float* X    = (const float*)d_in[0];   // [2,512,512]
    const float* Win  = (const float*)d_in[1];   // [512,512]
    const float* Wout = (const float*)d_in[2];   // [512,512]
    const float* Wb   = (const float*)d_in[3];   // [512,512]
    float* Y = (float*)d_out;                    // [2,512,512]

    dim3 grid(MTOK / BM, NTOT / BN);             // 16 x 24 = 384 CTAs
    gemm3_kernel<<<grid, 256>>>(X, Win, Wout, Wb);
    finalize_kernel<<<MTOK, 256>>>(X, Y);
}

// round 3
// speedup vs baseline: 1.3741x; 1.3741x over previous
#include <cuda_runtime.h>
#include <cstdint>

// Problem constants
#define B_    2
#define S_    512
#define D_    512
#define MTOK  1024          // B*S tokens
#define NTOT  1536          // w1 | w2 | w3
#define EPS_  1e-5f

__device__ float g_P[MTOK * NTOT];   // 6 MB scratch (static device arrays allowed)

// ---------------------------------------------------------------------------
// GEMM: P[m,n] = sum_k X[m,k] * W[n,k], via tf32x3 mma.sync (fp32 accuracy)
// CTA 256 thr, BM=128 BN=64 BK=16, warp tile 32x32 (m16n8k8 atoms 2x4)
// ---------------------------------------------------------------------------
#define BM 128
#define BN 64
#define BK 16
#define KPAD 20    // BK+4: conflict-free fragment LDS

__device__ __forceinline__ uint32_t f2tf32(float x) {
    uint32_t r;
    asm("cvt.rna.tf32.f32 %0, %1;" : "=r"(r) : "f"(x));
    return r;
}

__device__ __forceinline__ void cp16(uint32_t smem, const void* gmem) {
    asm volatile("cp.async.cg.shared.global [%0], [%1], 16;\n"
                 :: "r"(smem), "l"(gmem));
}

__device__ __forceinline__ void mma_tf32(float* c,
    uint32_t a0, uint32_t a1, uint32_t a2, uint32_t a3,
    uint32_t b0, uint32_t b1)
{
    asm volatile(
        "mma.sync.aligned.m16n8k8.row.col.f32.tf32.tf32.f32 "
        "{%0,%1,%2,%3}, {%4,%5,%6,%7}, {%8,%9}, {%0,%1,%2,%3};"
        : "+f"(c[0]), "+f"(c[1]), "+f"(c[2]), "+f"(c[3])
        : "r"(a0), "r"(a1), "r"(a2), "r"(a3), "r"(b0), "r"(b1));
}

__global__ __launch_bounds__(256, 2) void gemm3_tc(
    const float* __restrict__ X,
    const float* __restrict__ Win,
    const float* __restrict__ Wout,
    const float* __restrict__ Wb)
{
    __shared__ float As[2][BM * KPAD];
    __shared__ float Bs[2][BN * KPAD];

    const int tid   = threadIdx.x;
    const int lane  = tid & 31;
    const int wid   = tid >> 5;
    const int warpM = wid >> 1;         // 0..3
    const int warpN = wid & 1;          // 0..1
    const int gID   = lane >> 2;        // 0..7
    const int tIG   = lane & 3;         // 0..3
    const int m0    = blockIdx.x * BM;
    const int n0    = blockIdx.y * BN;

    const float* Wsel = (n0 < D_) ? Win : (n0 < 2 * D_ ? Wout : Wb);
    const int nb = n0 & (D_ - 1);

    const uint32_t sA = (uint32_t)__cvta_generic_to_shared(&As[0][0]);
    const uint32_t sB = (uint32_t)__cvta_generic_to_shared(&Bs[0][0]);

    float acc[2][4][4];
    #pragma unroll
    for (int i = 0; i < 2; i++)
        #pragma unroll
        for (int j = 0; j < 4; j++)
            #pragma unroll
            for (int q = 0; q < 4; q++) acc[i][j][q] = 0.f;

    // cp.async addressing (per-thread constants)
    const int arow0 = tid >> 2,  aq0 = tid & 3;   // 64 rows x 4 chunks
    const int arow1 = arow0 + 64;
    const int brow  = tid >> 2,  bq  = tid & 3;

    auto issue = [&](int t, int stg) {
        const int k0 = t * BK;
        cp16(sA + (uint32_t)(stg * BM * KPAD + arow0 * KPAD + aq0 * 4) * 4u,
             X + (m0 + arow0) * D_ + k0 + aq0 * 4);
        cp16(sA + (uint32_t)(stg * BM * KPAD + arow1 * KPAD + aq0 * 4) * 4u,
             X + (m0 + arow1) * D_ + k0 + aq0 * 4);
        cp16(sB + (uint32_t)(stg * BN * KPAD + brow * KPAD + bq * 4) * 4u,
             Wsel + (nb + brow) * D_ + k0 + bq * 4);
        asm volatile("cp.async.commit_group;");
    };

    auto compute = [&](int stg) {
        const float* Ab = &As[stg][0];
        const float* Bb = &Bs[stg][0];
        #pragma unroll
        for (int kk = 0; kk < BK; kk += 8) {
            uint32_t ahi[2][4], alo[2][4], bhi[4][2], blo[4][2];
            #pragma unroll
            for (int i = 0; i < 2; ++i) {
                const int r = warpM * 32 + i * 16 + gID;
                const int c = kk + tIG;
                float v0 = Ab[r * KPAD + c];
                float v1 = Ab[(r + 8) * KPAD + c];
                float v2 = Ab[r * KPAD + c + 4];
                float v3 = Ab[(r + 8) * KPAD + c + 4];
                ahi[i][0] = f2tf32(v0); alo[i][0] = __float_as_uint(v0 - __uint_as_float(ahi[i][0]));
                ahi[i][1] = f2tf32(v1); alo[i][1] = __float_as_uint(v1 - __uint_as_float(ahi[i][1]));
                ahi[i][2] = f2tf32(v2); alo[i][2] = __float_as_uint(v2 - __uint_as_float(ahi[i][2]));
                ahi[i][3] = f2tf32(v3); alo[i][3] = __float_as_uint(v3 - __uint_as_float(ahi[i][3]));
            }
            #pragma unroll
            for (int j = 0; j < 4; ++j) {
                const int n = warpN * 32 + j * 8 + gID;
                float u0 = Bb[n * KPAD + kk + tIG];
                float u1 = Bb[n * KPAD + kk + tIG + 4];
                bhi[j][0] = f2tf32(u0); blo[j][0] = __float_as_uint(u0 - __uint_as_float(bhi[j][0]));
                bhi[j][1] = f2tf32(u1); blo[j][1] = __float_as_uint(u1 - __uint_as_float(bhi[j][1]));
            }
            #pragma unroll
            for (int i = 0; i < 2; ++i)
                #pragma unroll
                for (int j = 0; j < 4; ++j) {
                    mma_tf32(acc[i][j], ahi[i][0], ahi[i][1], ahi[i][2], ahi[i][3],
                             blo[j][0], blo[j][1]);
                    mma_tf32(acc[i][j], alo[i][0], alo[i][1], alo[i][2], alo[i][3],
                             bhi[j][0], bhi[j][1]);
                    mma_tf32(acc[i][j], ahi[i][0], ahi[i][1], ahi[i][2], ahi[i][3],
                             bhi[j][0], bhi[j][1]);
                }
        }
    };

    constexpr int T = D_ / BK;   // 32
    issue(0, 0);
    #pragma unroll 1
    for (int t = 0; t < T; ++t) {
        if (t + 1 < T) {
            issue(t + 1, (t + 1) & 1);           // writes stage t+1 (other buffer)
            asm volatile("cp.async.wait_group 1;"); // stage t resident
        } else {
            asm volatile("cp.async.wait_group 0;");
        }
        __syncthreads();
        compute(t & 1);
        __syncthreads();
    }

    // Epilogue: write to g_P (float2 stores)
    #pragma unroll
    for (int i = 0; i < 2; ++i) {
        const int r = m0 + warpM * 32 + i * 16 + gID;
        #pragma unroll
        for (int j = 0; j < 4; ++j) {
            const int c = n0 + warpN * 32 + j * 8 + 2 * tIG;
            *reinterpret_cast<float2*>(&g_P[r * NTOT + c]) =
                make_float2(acc[i][j][0], acc[i][j][1]);
            *reinterpret_cast<float2*>(&g_P[(r + 8) * NTOT + c]) =
                make_float2(acc[i][j][2], acc[i][j][3]);
        }
    }
}

// ---------------------------------------------------------------------------
// Finalize: per-token closed-form (rank-1 LN collapse)
//   y_i = w2_i * (dot(w1,x) - mean(w1)*sum(x)) * rsqrt(w2_i^2*var(w1)+eps)
//       + (w3_i - mean(w3)) * rsqrt(var(w3)+eps)
// ---------------------------------------------------------------------------
__global__ __launch_bounds__(256) void finalize_kernel(
    const float* __restrict__ X, float* __restrict__ Y)
{
    __shared__ float red[6][8];
    const int m   = blockIdx.x;
    const int tid = threadIdx.x;
    const float* x = X + m * D_;
    const float* p = g_P + m * NTOT;   // w1 | w2 | w3

    const float2 a2  = *reinterpret_cast<const float2*>(&p[2 * tid]);
    const float2 xx2 = *reinterpret_cast<const float2*>(&x[2 * tid]);
    const float2 c2  = *reinterpret_cast<const float2*>(&p[2 * D_ + 2 * tid]);

    float sw1  = a2.x + a2.y;
    float sw1q = a2.x * a2.x + a2.y * a2.y;
    float sx   = xx2.x + xx2.y;
    float sw1x = a2.x * xx2.x + a2.y * xx2.y;
    float sw3  = c2.x + c2.y;
    float sw3q = c2.x * c2.x + c2.y * c2.y;

    #pragma unroll
    for (int o = 16; o; o >>= 1) {
        sw1  += __shfl_xor_sync(0xffffffffu, sw1,  o);
        sw1q += __shfl_xor_sync(0xffffffffu, sw1q, o);
        sx   += __shfl_xor_sync(0xffffffffu, sx,   o);
        sw1x += __shfl_xor_sync(0xffffffffu, sw1x, o);
        sw3  += __shfl_xor_sync(0xffffffffu, sw3,  o);
        sw3q += __shfl_xor_sync(0xffffffffu, sw3q, o);
    }
    const int warp = tid >> 5, lane = tid & 31;
    if (lane == 0) {
        red[0][warp] = sw1;  red[1][warp] = sw1q; red[2][warp] = sx;
        red[3][warp] = sw1x; red[4][warp] = sw3;  red[5][warp] = sw3q;
    }
    __syncthreads();

    float r[6];
    #pragma unroll
    for (int j = 0; j < 6; j++) {
        float t = 0.f;
        #pragma unroll
        for (int w = 0; w < 8; w++) t += red[j][w];
        r[j] = t;
    }

    const float invD = 1.0f / (float)D_;
    const float mu1  = r[0] * invD;
    const float var1 = fmaxf(r[1] * invD - mu1 * mu1, 0.f);
    const float s    = r[3] - mu1 * r[2];
    const float mu3  = r[4] * invD;
    const float var3 = fmaxf(r[5] * invD - mu3 * mu3, 0.f);
    const float inv3 = rsqrtf(var3 + EPS_);

    const float2 v2 = *reinterpret_cast<const float2*>(&p[D_ + 2 * tid]);
    float2 out;
    out.x = v2.x * s * rsqrtf(v2.x * v2.x * var1 + EPS_) + (c2.x - mu3) * inv3;
    out.y = v2.y * s * rsqrtf(v2.y * v2.y * var1 + EPS_) + (c2.y - mu3) * inv3;
    *reinterpret_cast<float2*>(&Y[m * D_ + 2 * tid]) = out;
}

// ---------------------------------------------------------------------------
extern "C" void kernel_launch(void* const* d_in, const int* in_sizes, int n_in,
                              void* d_out, int out_size)
{
    const float* X    = (const float*)d_in[0];
    const float* Win  = (const float*)d_in[1];
    const float* Wout = (const float*)d_in[2];
    const float* Wb   = (const float*)d_in[3];
    float* Y = (float*)d_out;

    dim3 grid(MTOK / BM, NTOT / BN);    // 8 x 24 = 192 CTAs
    gemm3_tc<<<grid, 256>>>(X, Win, Wout, Wb);
    finalize_kernel<<<MTOK, 256>>>(X, Y);
}

// round 5
// speedup vs baseline: 1.8493x; 1.3458x over previous
#include <cuda_runtime.h>
#include <cuda_fp16.h>
#include <cstdint>

// Problem constants
#define B_    2
#define S_    512
#define D_    512
#define MTOK  1024          // B*S tokens
#define NTOT  1536          // w1 | w2 | w3
#define EPS_  1e-5f

// Static device scratch (allocation APIs are forbidden)
__device__ float  g_P[MTOK * NTOT];     // 6 MB projections
__device__ __half g_A0[MTOK * D_];      // X hi split
__device__ __half g_A1[MTOK * D_];      // X lo split
__device__ __half g_B0[NTOT * D_];      // W concat hi split
__device__ __half g_B1[NTOT * D_];      // W concat lo split

// ---------------------------------------------------------------------------
// Kernel 0: split fp32 -> fp16 hi/lo (X and concatenated W)
// ---------------------------------------------------------------------------
#define XQ (MTOK * D_ / 4)     // 131072 float4 quads in X
#define WQ (NTOT * D_ / 4)     // 196608 quads in W concat

__global__ __launch_bounds__(256) void split_kernel(
    const float* __restrict__ X,
    const float* __restrict__ Win,
    const float* __restrict__ Wout,
    const float* __restrict__ Wb)
{
    const int idx = blockIdx.x * 256 + threadIdx.x;
    const float* src;
    __half *d0, *d1;
    if (idx < XQ) {
        src = X + idx * 4;
        d0 = g_A0 + idx * 4;  d1 = g_A1 + idx * 4;
    } else {
        const int j = idx - XQ;
        if (j >= WQ) return;
        const int q = j * 4;
        const int n = q >> 9;          // row in [0,1536)
        const int k = q & (D_ - 1);
        src = (n < D_ ? Win + n * D_
                      : (n < 2 * D_ ? Wout + (n - D_) * D_
                                    : Wb + (n - 2 * D_) * D_)) + k;
        d0 = g_B0 + q;  d1 = g_B1 + q;
    }
    const float4 v = *reinterpret_cast<const float4*>(src);
    __half h0 = __float2half_rn(v.x);
    __half h1 = __float2half_rn(v.y);
    __half h2 = __float2half_rn(v.z);
    __half h3 = __float2half_rn(v.w);
    __half l0 = __float2half_rn(v.x - __half2float(h0));
    __half l1 = __float2half_rn(v.y - __half2float(h1));
    __half l2 = __float2half_rn(v.z - __half2float(h2));
    __half l3 = __float2half_rn(v.w - __half2float(h3));
    reinterpret_cast<__half2*>(d0)[0] = __halves2half2(h0, h1);
    reinterpret_cast<__half2*>(d0)[1] = __halves2half2(h2, h3);
    reinterpret_cast<__half2*>(d1)[0] = __halves2half2(l0, l1);
    reinterpret_cast<__half2*>(d1)[1] = __halves2half2(l2, l3);
}

// ---------------------------------------------------------------------------
// Kernel 1: GEMM P[m,n] = sum_k X[m,k]*W[n,k] via fp16 3-pass split,
// mma.sync.m16n8k16. BM=128 BN=64 BK=32, 256 thr, warp tile 32x32.
// ---------------------------------------------------------------------------
#define BM 128
#define BN 64
#define BK 32
#define KP 40                       // halves per smem row (80B): conflict-free
#define A_OFF  0                    // half offsets within a stage
#define A1_OFF (BM * KP)            // 5120
#define B_OFF  (2 * BM * KP)        // 10240
#define B1_OFF (2 * BM * KP + BN * KP)  // 12800
#define STAGE_H (2 * BM * KP + 2 * BN * KP)   // 15360 halves = 30720 B
#define GSMEM   (2 * STAGE_H * 2)             // 61440 B

__device__ __forceinline__ void cp16(uint32_t smem, const void* gmem) {
    asm volatile("cp.async.cg.shared.global [%0], [%1], 16;\n"
                 :: "r"(smem), "l"(gmem));
}

__device__ __forceinline__ void mma_f16(float* c,
    uint32_t a0, uint32_t a1, uint32_t a2, uint32_t a3,
    uint32_t b0, uint32_t b1)
{
    asm volatile(
        "mma.sync.aligned.m16n8k16.row.col.f32.f16.f16.f32 "
        "{%0,%1,%2,%3}, {%4,%5,%6,%7}, {%8,%9}, {%0,%1,%2,%3};"
        : "+f"(c[0]), "+f"(c[1]), "+f"(c[2]), "+f"(c[3])
        : "r"(a0), "r"(a1), "r"(a2), "r"(a3), "r"(b0), "r"(b1));
}

__global__ __launch_bounds__(256, 2) void gemm3_f16()
{
    extern __shared__ __half sm[];

    const int tid   = threadIdx.x;
    const int lane  = tid & 31;
    const int wid   = tid >> 5;
    const int warpM = wid >> 1;         // 0..3
    const int warpN = wid & 1;          // 0..1
    const int gID   = lane >> 2;        // 0..7
    const int tIG   = lane & 3;         // 0..3
    const int m0    = blockIdx.x * BM;
    const int n0    = blockIdx.y * BN;

    const uint32_t sbase = (uint32_t)__cvta_generic_to_shared(sm);

    float acc[2][4][4];
    #pragma unroll
    for (int i = 0; i < 2; i++)
        #pragma unroll
        for (int j = 0; j < 4; j++)
            #pragma unroll
            for (int q = 0; q < 4; q++) acc[i][j][q] = 0.f;

    // cp.async addressing constants
    const int arow = tid >> 2, aq = tid & 3;        // A: 2 chunks/thread/array
    const int brow = tid >> 2, bq = tid & 3;        // B: 1 chunk/thread/array

    auto issue = [&](int t, int stg) {
        const int k0 = t * BK;
        const uint32_t st = sbase + (uint32_t)(stg * STAGE_H) * 2u;
        // A0 / A1: 128 rows x 4 chunks = 512 chunks each
        #pragma unroll
        for (int it = 0; it < 2; ++it) {
            const int r = arow + it * 64;
            const uint32_t so = (uint32_t)(r * KP + aq * 8) * 2u;
            cp16(st + A_OFF * 2u + so,  g_A0 + (m0 + r) * D_ + k0 + aq * 8);
            cp16(st + A1_OFF * 2u + so, g_A1 + (m0 + r) * D_ + k0 + aq * 8);
        }
        // B0 / B1: 64 rows x 4 chunks = 256 chunks each
        {
            const uint32_t so = (uint32_t)(brow * KP + bq * 8) * 2u;
            cp16(st + B_OFF * 2u + so,  g_B0 + (n0 + brow) * D_ + k0 + bq * 8);
            cp16(st + B1_OFF * 2u + so, g_B1 + (n0 + brow) * D_ + k0 + bq * 8);
        }
        asm volatile("cp.async.commit_group;");
    };

    auto compute = [&](int stg) {
        const __half* Ah = sm + stg * STAGE_H + A_OFF;
        const __half* Al = sm + stg * STAGE_H + A1_OFF;
        const __half* Bh = sm + stg * STAGE_H + B_OFF;
        const __half* Bl = sm + stg * STAGE_H + B1_OFF;
        #pragma unroll
        for (int kk = 0; kk < BK; kk += 16) {
            uint32_t ah[2][4], al[2][4], bh[4][2], bl[4][2];
            #pragma unroll
            for (int i = 0; i < 2; ++i) {
                const int r = warpM * 32 + i * 16 + gID;
                const int c = kk + 2 * tIG;
                ah[i][0] = *(const uint32_t*)&Ah[r * KP + c];
                ah[i][1] = *(const uint32_t*)&Ah[(r + 8) * KP + c];
                ah[i][2] = *(const uint32_t*)&Ah[r * KP + c + 8];
                ah[i][3] = *(const uint32_t*)&Ah[(r + 8) * KP + c + 8];
                al[i][0] = *(const uint32_t*)&Al[r * KP + c];
                al[i][1] = *(const uint32_t*)&Al[(r + 8) * KP + c];
                al[i][2] = *(const uint32_t*)&Al[r * KP + c + 8];
                al[i][3] = *(const uint32_t*)&Al[(r + 8) * KP + c + 8];
            }
            #pragma unroll
            for (int j = 0; j < 4; ++j) {
                const int n = warpN * 32 + j * 8 + gID;
                const int c = kk + 2 * tIG;
                bh[j][0] = *(const uint32_t*)&Bh[n * KP + c];
                bh[j][1] = *(const uint32_t*)&Bh[n * KP + c + 8];
                bl[j][0] = *(const uint32_t*)&Bl[n * KP + c];
                bl[j][1] = *(const uint32_t*)&Bl[n * KP + c + 8];
            }
            #pragma unroll
            for (int i = 0; i < 2; ++i)
                #pragma unroll
                for (int j = 0; j < 4; ++j) {
                    mma_f16(acc[i][j], ah[i][0], ah[i][1], ah[i][2], ah[i][3],
                            bl[j][0], bl[j][1]);                    // hi*lo
                    mma_f16(acc[i][j], al[i][0], al[i][1], al[i][2], al[i][3],
                            bh[j][0], bh[j][1]);                    // lo*hi
                    mma_f16(acc[i][j], ah[i][0], ah[i][1], ah[i][2], ah[i][3],
                            bh[j][0], bh[j][1]);                    // hi*hi
                }
        }
    };

    constexpr int T = D_ / BK;   // 16
    issue(0, 0);
    #pragma unroll 1
    for (int t = 0; t < T; ++t) {
        if (t + 1 < T) {
            issue(t + 1, (t + 1) & 1);               // fills the other buffer
            asm volatile("cp.async.wait_group 1;");  // stage t resident
        } else {
            asm volatile("cp.async.wait_group 0;");
        }
        __syncthreads();
        compute(t & 1);
        __syncthreads();
    }

    // Epilogue: float2 stores to g_P
    #pragma unroll
    for (int i = 0; i < 2; ++i) {
        const int r = m0 + warpM * 32 + i * 16 + gID;
        #pragma unroll
        for (int j = 0; j < 4; ++j) {
            const int c = n0 + warpN * 32 + j * 8 + 2 * tIG;
            *reinterpret_cast<float2*>(&g_P[r * NTOT + c]) =
                make_float2(acc[i][j][0], acc[i][j][1]);
            *reinterpret_cast<float2*>(&g_P[(r + 8) * NTOT + c]) =
                make_float2(acc[i][j][2], acc[i][j][3]);
        }
    }
}

// ---------------------------------------------------------------------------
// Kernel 2: per-token closed-form epilogue (rank-1 LN collapse)
//   y_i = w2_i*(dot(w1,x)-mean(w1)*sum(x))*rsqrt(w2_i^2*var(w1)+eps)
//       + (w3_i-mean(w3))*rsqrt(var(w3)+eps)
// ---------------------------------------------------------------------------
__global__ __launch_bounds__(256) void finalize_kernel(
    const float* __restrict__ X, float* __restrict__ Y)
{
    __shared__ float red[6][8];
    const int m   = blockIdx.x;
    const int tid = threadIdx.x;
    const float* x = X + m * D_;
    const float* p = g_P + m * NTOT;   // w1 | w2 | w3

    const float2 a2  = *reinterpret_cast<const float2*>(&p[2 * tid]);
    const float2 xx2 = *reinterpret_cast<const float2*>(&x[2 * tid]);
    const float2 c2  = *reinterpret_cast<const float2*>(&p[2 * D_ + 2 * tid]);

    float sw1  = a2.x + a2.y;
    float sw1q = a2.x * a2.x + a2.y * a2.y;
    float sx   = xx2.x + xx2.y;
    float sw1x = a2.x * xx2.x + a2.y * xx2.y;
    float sw3  = c2.x + c2.y;
    float sw3q = c2.x * c2.x + c2.y * c2.y;

    #pragma unroll
    for (int o = 16; o; o >>= 1) {
        sw1  += __shfl_xor_sync(0xffffffffu, sw1,  o);
        sw1q += __shfl_xor_sync(0xffffffffu, sw1q, o);
        sx   += __shfl_xor_sync(0xffffffffu, sx,   o);
        sw1x += __shfl_xor_sync(0xffffffffu, sw1x, o);
        sw3  += __shfl_xor_sync(0xffffffffu, sw3,  o);
        sw3q += __shfl_xor_sync(0xffffffffu, sw3q, o);
    }
    const int warp = tid >> 5, lane = tid & 31;
    if (lane == 0) {
        red[0][warp] = sw1;  red[1][warp] = sw1q; red[2][warp] = sx;
        red[3][warp] = sw1x; red[4][warp] = sw3;  red[5][warp] = sw3q;
    }
    __syncthreads();

    float r[6];
    #pragma unroll
    for (int j = 0; j < 6; j++) {
        float t = 0.f;
        #pragma unroll
        for (int w = 0; w < 8; w++) t += red[j][w];
        r[j] = t;
    }

    const float invD = 1.0f / (float)D_;
    const float mu1  = r[0] * invD;
    const float var1 = fmaxf(r[1] * invD - mu1 * mu1, 0.f);
    const float s    = r[3] - mu1 * r[2];
    const float mu3  = r[4] * invD;
    const float var3 = fmaxf(r[5] * invD - mu3 * mu3, 0.f);
    const float inv3 = rsqrtf(var3 + EPS_);

    const float2 v2 = *reinterpret_cast<const float2*>(&p[D_ + 2 * tid]);
    float2 out;
    out.x = v2.x * s * rsqrtf(v2.x * v2.x * var1 + EPS_) + (c2.x - mu3) * inv3;
    out.y = v2.y * s * rsqrtf(v2.y * v2.y * var1 + EPS_) + (c2.y - mu3) * inv3;
    *reinterpret_cast<float2*>(&Y[m * D_ + 2 * tid]) = out;
}

// ---------------------------------------------------------------------------
extern "C" void kernel_launch(void* const* d_in, const int* in_sizes, int n_in,
                              void* d_out, int out_size)
{
    const float* X    = (const float*)d_in[0];
    const float* Win  = (const float*)d_in[1];
    const float* Wout = (const float*)d_in[2];
    const float* Wb   = (const float*)d_in[3];
    float* Y = (float*)d_out;

    cudaFuncSetAttribute(gemm3_f16,
                         cudaFuncAttributeMaxDynamicSharedMemorySize, GSMEM);

    const int totalQ = XQ + WQ;
    split_kernel<<<(totalQ + 255) / 256, 256>>>(X, Win, Wout, Wb);
    gemm3_f16<<<dim3(MTOK / BM, NTOT / BN), 256, GSMEM>>>();
    finalize_kernel<<<MTOK, 256>>>(X, Y);
}

// round 6
// speedup vs baseline: 2.4423x; 1.3206x over previous
#include <cuda_runtime.h>
#include <cuda_fp16.h>
#include <cstdint>

// Problem constants
#define B_    2
#define S_    512
#define D_    512
#define MTOK  1024          // B*S tokens
#define NTOT  1536          // w1 | w2 | w3
#define EPS_  1e-5f

// Static device scratch
__device__ float  g_P[MTOK * NTOT];     // 6 MB projections
__device__ __half g_A0[MTOK * D_];      // X hi split
__device__ __half g_A1[MTOK * D_];      // X lo split
__device__ __half g_B0[NTOT * D_];      // W concat hi split
__device__ __half g_B1[NTOT * D_];      // W concat lo split

// ---------------------------------------------------------------------------
// Kernel 0: split fp32 -> fp16 hi/lo. 8 floats per thread, 16B stores.
// ---------------------------------------------------------------------------
#define XFL   (MTOK * D_)              // 524288 floats in X
#define TOTG  ((MTOK + NTOT) * D_ / 8) // 163840 groups of 8

__global__ __launch_bounds__(256) void split_kernel(
    const float* __restrict__ X,
    const float* __restrict__ Win,
    const float* __restrict__ Wout,
    const float* __restrict__ Wb)
{
    const int g = blockIdx.x * 256 + threadIdx.x;
    if (g >= TOTG) return;
    const int q = g * 8;

    const float* src;
    __half *d0, *d1;
    if (q < XFL) {
        src = X + q;
        d0 = g_A0 + q;  d1 = g_A1 + q;
    } else {
        const int wq = q - XFL;
        const int n  = wq >> 9;
        const int k  = wq & (D_ - 1);
        src = (n < D_ ? Win + n * D_
                      : (n < 2 * D_ ? Wout + (n - D_) * D_
                                    : Wb + (n - 2 * D_) * D_)) + k;
        d0 = g_B0 + wq;  d1 = g_B1 + wq;
    }
    const float4 v0 = reinterpret_cast<const float4*>(src)[0];
    const float4 v1 = reinterpret_cast<const float4*>(src)[1];
    float f[8] = {v0.x, v0.y, v0.z, v0.w, v1.x, v1.y, v1.z, v1.w};
    __half hi[8], lo[8];
    #pragma unroll
    for (int i = 0; i < 8; ++i) {
        hi[i] = __float2half_rn(f[i]);
        lo[i] = __float2half_rn(f[i] - __half2float(hi[i]));
    }
    uint4 sh, sl;
    sh.x = *(uint32_t*)&hi[0]; sh.y = *(uint32_t*)&hi[2];
    sh.z = *(uint32_t*)&hi[4]; sh.w = *(uint32_t*)&hi[6];
    sl.x = *(uint32_t*)&lo[0]; sl.y = *(uint32_t*)&lo[2];
    sl.z = *(uint32_t*)&lo[4]; sl.w = *(uint32_t*)&lo[6];
    *reinterpret_cast<uint4*>(d0) = sh;
    *reinterpret_cast<uint4*>(d1) = sl;
}

// ---------------------------------------------------------------------------
// Kernel 1: GEMM P[m,n] = sum_k X[m,k]*W[n,k], fp16 3-pass split, HMMA.16816.
// BM=128 BN=96 BK=32, grid 8x16 = 128 CTAs (one uniform wave on 148 SMs).
// 8 warps (4 M x 2 N), warp tile 32x48 (2x6 m16n8 atoms).
// ---------------------------------------------------------------------------
#define BM 128
#define BN 96
#define BK 32
#define KP 40                          // halves per smem row: conflict-free
#define A_OFF   0
#define A1_OFF  (BM * KP)              // 5120
#define B_OFF   (2 * BM * KP)          // 10240
#define B1_OFF  (2 * BM * KP + BN * KP) // 14080
#define STAGE_H (2 * BM * KP + 2 * BN * KP)  // 17920 halves
#define GSMEM   (2 * STAGE_H * 2)            // 71680 B

__device__ __forceinline__ void cp16(uint32_t smem, const void* gmem) {
    asm volatile("cp.async.cg.shared.global [%0], [%1], 16;\n"
                 :: "r"(smem), "l"(gmem));
}

__device__ __forceinline__ void mma_f16(float* c,
    uint32_t a0, uint32_t a1, uint32_t a2, uint32_t a3,
    uint32_t b0, uint32_t b1)
{
    asm volatile(
        "mma.sync.aligned.m16n8k16.row.col.f32.f16.f16.f32 "
        "{%0,%1,%2,%3}, {%4,%5,%6,%7}, {%8,%9}, {%0,%1,%2,%3};"
        : "+f"(c[0]), "+f"(c[1]), "+f"(c[2]), "+f"(c[3])
        : "r"(a0), "r"(a1), "r"(a2), "r"(a3), "r"(b0), "r"(b1));
}

__global__ __launch_bounds__(256, 1) void gemm3_f16()
{
    extern __shared__ __half sm[];

    const int tid   = threadIdx.x;
    const int lane  = tid & 31;
    const int wid   = tid >> 5;
    const int warpM = wid >> 1;         // 0..3
    const int warpN = wid & 1;          // 0..1
    const int gID   = lane >> 2;        // 0..7
    const int tIG   = lane & 3;         // 0..3
    const int m0    = blockIdx.x * BM;
    const int n0    = blockIdx.y * BN;

    const uint32_t sbase = (uint32_t)__cvta_generic_to_shared(sm);

    float acc[2][6][4];
    #pragma unroll
    for (int i = 0; i < 2; i++)
        #pragma unroll
        for (int j = 0; j < 6; j++)
            #pragma unroll
            for (int q = 0; q < 4; q++) acc[i][j][q] = 0.f;

    auto issue = [&](int t, int stg) {
        const int k0 = t * BK;
        const uint32_t st = sbase + (uint32_t)(stg * STAGE_H) * 2u;
        // A0/A1: 512 chunks each (128 rows x 4 chunks of 8 halves)
        #pragma unroll
        for (int it = 0; it < 2; ++it) {
            const int c = tid + it * 256;
            const int r = c >> 2, qd = c & 3;
            const uint32_t so = (uint32_t)(r * KP + qd * 8) * 2u;
            cp16(st + A_OFF * 2u + so,  g_A0 + (m0 + r) * D_ + k0 + qd * 8);
            cp16(st + A1_OFF * 2u + so, g_A1 + (m0 + r) * D_ + k0 + qd * 8);
        }
        // B0/B1: 384 chunks each (96 rows x 4 chunks)
        #pragma unroll
        for (int c = tid; c < 384; c += 256) {
            const int r = c >> 2, qd = c & 3;
            const uint32_t so = (uint32_t)(r * KP + qd * 8) * 2u;
            cp16(st + B_OFF * 2u + so,  g_B0 + (n0 + r) * D_ + k0 + qd * 8);
            cp16(st + B1_OFF * 2u + so, g_B1 + (n0 + r) * D_ + k0 + qd * 8);
        }
        asm volatile("cp.async.commit_group;");
    };

    auto compute = [&](int stg) {
        const __half* Ah = sm + stg * STAGE_H + A_OFF;
        const __half* Al = sm + stg * STAGE_H + A1_OFF;
        const __half* Bh = sm + stg * STAGE_H + B_OFF;
        const __half* Bl = sm + stg * STAGE_H + B1_OFF;
        #pragma unroll
        for (int kk = 0; kk < BK; kk += 16) {
            uint32_t ah[2][4], al[2][4], bh[6][2], bl[6][2];
            #pragma unroll
            for (int i = 0; i < 2; ++i) {
                const int r = warpM * 32 + i * 16 + gID;
                const int c = kk + 2 * tIG;
                ah[i][0] = *(const uint32_t*)&Ah[r * KP + c];
                ah[i][1] = *(const uint32_t*)&Ah[(r + 8) * KP + c];
                ah[i][2] = *(const uint32_t*)&Ah[r * KP + c + 8];
                ah[i][3] = *(const uint32_t*)&Ah[(r + 8) * KP + c + 8];
                al[i][0] = *(const uint32_t*)&Al[r * KP + c];
                al[i][1] = *(const uint32_t*)&Al[(r + 8) * KP + c];
                al[i][2] = *(const uint32_t*)&Al[r * KP + c + 8];
                al[i][3] = *(const uint32_t*)&Al[(r + 8) * KP + c + 8];
            }
            #pragma unroll
            for (int j = 0; j < 6; ++j) {
                const int n = warpN * 48 + j * 8 + gID;
                const int c = kk + 2 * tIG;
                bh[j][0] = *(const uint32_t*)&Bh[n * KP + c];
                bh[j][1] = *(const uint32_t*)&Bh[n * KP + c + 8];
                bl[j][0] = *(const uint32_t*)&Bl[n * KP + c];
                bl[j][1] = *(const uint32_t*)&Bl[n * KP + c + 8];
            }
            // Pass-major: 12 independent accumulators between touches of the
            // same acc -> no RAW stalls regardless of scheduler.
            #pragma unroll
            for (int i = 0; i < 2; ++i)
                #pragma unroll
                for (int j = 0; j < 6; ++j)
                    mma_f16(acc[i][j], ah[i][0], ah[i][1], ah[i][2], ah[i][3],
                            bl[j][0], bl[j][1]);                    // hi*lo
            #pragma unroll
            for (int i = 0; i < 2; ++i)
                #pragma unroll
                for (int j = 0; j < 6; ++j)
                    mma_f16(acc[i][j], al[i][0], al[i][1], al[i][2], al[i][3],
                            bh[j][0], bh[j][1]);                    // lo*hi
            #pragma unroll
            for (int i = 0; i < 2; ++i)
                #pragma unroll
                for (int j = 0; j < 6; ++j)
                    mma_f16(acc[i][j], ah[i][0], ah[i][1], ah[i][2], ah[i][3],
                            bh[j][0], bh[j][1]);                    // hi*hi
        }
    };

    constexpr int T = D_ / BK;   // 16
    issue(0, 0);
    #pragma unroll 1
    for (int t = 0; t < T; ++t) {
        if (t + 1 < T) {
            issue(t + 1, (t + 1) & 1);
            asm volatile("cp.async.wait_group 1;");
        } else {
            asm volatile("cp.async.wait_group 0;");
        }
        __syncthreads();
        compute(t & 1);
        __syncthreads();
    }

    // Epilogue: float2 stores to g_P
    #pragma unroll
    for (int i = 0; i < 2; ++i) {
        const int r = m0 + warpM * 32 + i * 16 + gID;
        #pragma unroll
        for (int j = 0; j < 6; ++j) {
            const int c = n0 + warpN * 48 + j * 8 + 2 * tIG;
            *reinterpret_cast<float2*>(&g_P[r * NTOT + c]) =
                make_float2(acc[i][j][0], acc[i][j][1]);
            *reinterpret_cast<float2*>(&g_P[(r + 8) * NTOT + c]) =
                make_float2(acc[i][j][2], acc[i][j][3]);
        }
    }
}

// ---------------------------------------------------------------------------
// Kernel 2: per-token closed-form epilogue (rank-1 LN collapse).
// 1024 blocks x 128 threads, float4 everywhere.
// ---------------------------------------------------------------------------
__global__ __launch_bounds__(128) void finalize_kernel(
    const float* __restrict__ X, float* __restrict__ Y)
{
    __shared__ float red[6][4];
    const int m   = blockIdx.x;
    const int tid = threadIdx.x;
    const float* x = X + m * D_;
    const float* p = g_P + m * NTOT;   // w1 | w2 | w3

    const float4 a4  = *reinterpret_cast<const float4*>(&p[4 * tid]);
    const float4 x4  = *reinterpret_cast<const float4*>(&x[4 * tid]);
    const float4 c4  = *reinterpret_cast<const float4*>(&p[2 * D_ + 4 * tid]);

    float sw1  = (a4.x + a4.y) + (a4.z + a4.w);
    float sw1q = (a4.x * a4.x + a4.y * a4.y) + (a4.z * a4.z + a4.w * a4.w);
    float sx   = (x4.x + x4.y) + (x4.z + x4.w);
    float sw1x = (a4.x * x4.x + a4.y * x4.y) + (a4.z * x4.z + a4.w * x4.w);
    float sw3  = (c4.x + c4.y) + (c4.z + c4.w);
    float sw3q = (c4.x * c4.x + c4.y * c4.y) + (c4.z * c4.z + c4.w * c4.w);

    #pragma unroll
    for (int o = 16; o; o >>= 1) {
        sw1  += __shfl_xor_sync(0xffffffffu, sw1,  o);
        sw1q += __shfl_xor_sync(0xffffffffu, sw1q, o);
        sx   += __shfl_xor_sync(0xffffffffu, sx,   o);
        sw1x += __shfl_xor_sync(0xffffffffu, sw1x, o);
        sw3  += __shfl_xor_sync(0xffffffffu, sw3,  o);
        sw3q += __shfl_xor_sync(0xffffffffu, sw3q, o);
    }
    const int warp = tid >> 5, lane = tid & 31;
    if (lane == 0) {
        red[0][warp] = sw1;  red[1][warp] = sw1q; red[2][warp] = sx;
        red[3][warp] = sw1x; red[4][warp] = sw3;  red[5][warp] = sw3q;
    }
    __syncthreads();

    float r[6];
    #pragma unroll
    for (int j = 0; j < 6; j++)
        r[j] = (red[j][0] + red[j][1]) + (red[j][2] + red[j][3]);

    const float invD = 1.0f / (float)D_;
    const float mu1  = r[0] * invD;
    const float var1 = fmaxf(r[1] * invD - mu1 * mu1, 0.f);
    const float s    = r[3] - mu1 * r[2];
    const float mu3  = r[4] * invD;
    const float var3 = fmaxf(r[5] * invD - mu3 * mu3, 0.f);
    const float inv3 = rsqrtf(var3 + EPS_);

    const float4 v4 = *reinterpret_cast<const float4*>(&p[D_ + 4 * tid]);
    float4 out;
    out.x = v4.x * s * rsqrtf(v4.x * v4.x * var1 + EPS_) + (c4.x - mu3) * inv3;
    out.y = v4.y * s * rsqrtf(v4.y * v4.y * var1 + EPS_) + (c4.y - mu3) * inv3;
    out.z = v4.z * s * rsqrtf(v4.z * v4.z * var1 + EPS_) + (c4.z - mu3) * inv3;
    out.w = v4.w * s * rsqrtf(v4.w * v4.w * var1 + EPS_) + (c4.w - mu3) * inv3;
    *reinterpret_cast<float4*>(&Y[m * D_ + 4 * tid]) = out;
}

// ---------------------------------------------------------------------------
extern "C" void kernel_launch(void* const* d_in, const int* in_sizes, int n_in,
                              void* d_out, int out_size)
{
    const float* X    = (const float*)d_in[0];
    const float* Win  = (const float*)d_in[1];
    const float* Wout = (const float*)d_in[2];
    const float* Wb   = (const float*)d_in[3];
    float* Y = (float*)d_out;

    cudaFuncSetAttribute(gemm3_f16,
                         cudaFuncAttributeMaxDynamicSharedMemorySize, GSMEM);

    split_kernel<<<(TOTG + 255) / 256, 256>>>(X, Win, Wout, Wb);
    gemm3_f16<<<dim3(MTOK / BM, NTOT / BN), 256, GSMEM>>>();
    finalize_kernel<<<MTOK, 128>>>(X, Y);
}